// round 2
// baseline (speedup 1.0000x reference)
#include <cuda_runtime.h>

// Scratch (device globals — no runtime allocation allowed)
__device__ float g_part   [4 * 32 * 1024];  // partial column sums of v
__device__ float g_rowsum [4 * 1024];       // vsum @ Wv  (per-head V sums)
__device__ float g_wosum  [64 * 1024];      // WoSum[d][m] = sum_j Wo[j*64+d][m]
__device__ float g_outrows[64 * 1024];      // 16 distinct out rows per batch

// K1: partial column sums of v: part[b][s][c] = sum_{l in [s*32,(s+1)*32)} v[b][l][c]
__global__ __launch_bounds__(1024) void colsum_kernel(const float* __restrict__ v,
                                                      float* __restrict__ part) {
    const int s = blockIdx.x, b = blockIdx.y, c = threadIdx.x;
    const float* p = v + ((size_t)(b * 1024 + s * 32)) * 1024 + c;
    float acc = 0.f;
#pragma unroll
    for (int i = 0; i < 32; ++i) acc += p[(size_t)i * 1024];
    part[(b * 32 + s) * 1024 + c] = acc;
}

// K0: zero rowsum accumulator (graph replays must not depend on initial state)
__global__ void zero_kernel(float* __restrict__ p) {
    p[blockIdx.x * 1024 + threadIdx.x] = 0.f;
}

// K2: rowsum[b][o] = sum_k vsum[b][k] * Wv[k][o]   (vsum reduced from partials)
__global__ __launch_bounds__(256) void vwv_kernel(const float* __restrict__ part,
                                                  const float* __restrict__ Wv,
                                                  float* __restrict__ rowsum) {
    __shared__ float vs[4][128];
    const int oc = blockIdx.x, kc = blockIdx.y, t = threadIdx.x;
    for (int idx = t; idx < 512; idx += 256) {
        int b = idx >> 7, kk = idx & 127;
        int k = kc * 128 + kk;
        float a = 0.f;
#pragma unroll
        for (int s = 0; s < 32; ++s) a += part[(b * 32 + s) * 1024 + k];
        vs[b][kk] = a;
    }
    __syncthreads();
    const int o = oc * 256 + t;
    float a0 = 0.f, a1 = 0.f, a2 = 0.f, a3 = 0.f;
#pragma unroll 8
    for (int kk = 0; kk < 128; ++kk) {
        float w = Wv[(size_t)(kc * 128 + kk) * 1024 + o];
        a0 = fmaf(vs[0][kk], w, a0);
        a1 = fmaf(vs[1][kk], w, a1);
        a2 = fmaf(vs[2][kk], w, a2);
        a3 = fmaf(vs[3][kk], w, a3);
    }
    atomicAdd(&rowsum[0 * 1024 + o], a0);
    atomicAdd(&rowsum[1 * 1024 + o], a1);
    atomicAdd(&rowsum[2 * 1024 + o], a2);
    atomicAdd(&rowsum[3 * 1024 + o], a3);
}

// K3: WoSum[d][m] = sum_{j<16} Wo[(j*64+d)][m]
__global__ __launch_bounds__(256) void wosum_kernel(const float* __restrict__ Wo,
                                                    float* __restrict__ wosum) {
    const int idx = blockIdx.x * 256 + threadIdx.x;  // 0..65535
    const int d = idx >> 10, m = idx & 1023;
    float a = 0.f;
#pragma unroll
    for (int j = 0; j < 16; ++j) a += Wo[(size_t)(j * 64 + d) * 1024 + m];
    wosum[idx] = a;
}

// K4: outrows[bn][m] = sum_d rowsum[b][n*64+d] * WoSum[d][m]
__global__ __launch_bounds__(256) void outrows_kernel(const float* __restrict__ rowsum,
                                                      const float* __restrict__ wosum,
                                                      float* __restrict__ outrows) {
    __shared__ float rs[64];
    const int mc = blockIdx.x, bn = blockIdx.y, t = threadIdx.x;
    if (t < 64) rs[t] = rowsum[(bn >> 4) * 1024 + (bn & 15) * 64 + t];
    __syncthreads();
    const int m = mc * 256 + t;
    float a = 0.f;
#pragma unroll
    for (int d = 0; d < 64; ++d) a = fmaf(rs[d], wosum[d * 1024 + m], a);
    outrows[bn * 1024 + m] = a;
}

// K5: residual add + LayerNorm. Row (b,l) uses outrows[b*16 + l/64].
__global__ __launch_bounds__(256) void ln_kernel(const float* __restrict__ outrows,
                                                 const float* __restrict__ q,
                                                 const float* __restrict__ gamma,
                                                 const float* __restrict__ beta,
                                                 float* __restrict__ out) {
    __shared__ float wsum[8], wsq[8], stat[2];
    const int row = blockIdx.x;
    const int tid = threadIdx.x;
    const int bn = (row >> 10) * 16 + ((row & 1023) >> 6);

    float4 y = ((const float4*)(outrows + (size_t)bn * 1024))[tid];
    float4 r = ((const float4*)(q + (size_t)row * 1024))[tid];
    float x0 = y.x + r.x, x1 = y.y + r.y, x2 = y.z + r.z, x3 = y.w + r.w;

    float s  = x0 + x1 + x2 + x3;
    float sq = x0 * x0 + x1 * x1 + x2 * x2 + x3 * x3;
#pragma unroll
    for (int off = 16; off >= 1; off >>= 1) {
        s  += __shfl_xor_sync(0xffffffffu, s,  off);
        sq += __shfl_xor_sync(0xffffffffu, sq, off);
    }
    if ((tid & 31) == 0) { wsum[tid >> 5] = s; wsq[tid >> 5] = sq; }
    __syncthreads();
    if (tid == 0) {
        float S = 0.f, Qm = 0.f;
#pragma unroll
        for (int w = 0; w < 8; ++w) { S += wsum[w]; Qm += wsq[w]; }
        float mean = S * (1.f / 1024.f);
        float var  = Qm * (1.f / 1024.f) - mean * mean;
        stat[0] = mean;
        stat[1] = rsqrtf(var + 1e-6f);
    }
    __syncthreads();
    float mean = stat[0], inv = stat[1];
    float4 g  = ((const float4*)gamma)[tid];
    float4 bt = ((const float4*)beta)[tid];
    float4 o4 = make_float4((x0 - mean) * inv * g.x + bt.x,
                            (x1 - mean) * inv * g.y + bt.y,
                            (x2 - mean) * inv * g.z + bt.z,
                            (x3 - mean) * inv * g.w + bt.w);
    ((float4*)(out + (size_t)row * 1024))[tid] = o4;
}

// ---------------------------------------------------------------------------
extern "C" void kernel_launch(void* const* d_in, const int* in_sizes, int n_in,
                              void* d_out, int out_size) {
    (void)in_sizes; (void)n_in; (void)out_size;
    const float* q     = (const float*)d_in[0];
    const float* v     = (const float*)d_in[2];
    const float* Wv    = (const float*)d_in[6];
    const float* Wo    = (const float*)d_in[7];
    const float* gamma = (const float*)d_in[8];
    const float* beta  = (const float*)d_in[9];
    float* out = (float*)d_out;

    float *part, *rowsum, *wosum, *outrows;
    cudaGetSymbolAddress((void**)&part,    g_part);
    cudaGetSymbolAddress((void**)&rowsum,  g_rowsum);
    cudaGetSymbolAddress((void**)&wosum,   g_wosum);
    cudaGetSymbolAddress((void**)&outrows, g_outrows);

    colsum_kernel<<<dim3(32, 4), 1024>>>(v, part);
    zero_kernel<<<4, 1024>>>(rowsum);
    vwv_kernel<<<dim3(4, 8), 256>>>(part, Wv, rowsum);
    wosum_kernel<<<256, 256>>>(Wo, wosum);
    outrows_kernel<<<dim3(4, 64), 256>>>(rowsum, wosum, outrows);
    ln_kernel<<<4096, 256>>>(outrows, q, gamma, beta, out);
}